// round 1
// baseline (speedup 1.0000x reference)
#include <cuda_runtime.h>
#include <math.h>
#include <stdint.h>

// Problem constants
#define BATCH   2
#define S_LEN   2048
#define D_DIM   2048
#define NQH     16
#define NKVH    8
#define HD      256
#define WINDOW  1024

// qkv concat width: 16*256 (q) + 8*256 (k) + 8*256 (v) = 8192
#define QKV_W   8192
#define TOKENS  (BATCH * S_LEN)          // 4096

// Scratch (device globals — no allocation allowed)
__device__ float g_tmp[(size_t)TOKENS * QKV_W];      // qkv projections (rope applied in place)
__device__ float g_av [(size_t)TOKENS * (NQH * HD)]; // attention output [b,t,n*256+h]

// ---------------------------------------------------------------------------
// SGEMM: 128x128 tile, BK=16, 256 threads, 8x8 per thread.
// mode 0: C[4096,8192] = x[4096,2048] @ Wcat    (per-128-col tile maps to one head of Wq/Wk/Wv)
// mode 1: C[4096,2048] = g_av[4096,4096] @ Wo   (Wo [NQ,H,D] is row-major [4096,2048])
// ---------------------------------------------------------------------------
__global__ __launch_bounds__(256) void sgemm_kernel(
    const float* __restrict__ x,
    const float* __restrict__ Wq,
    const float* __restrict__ Wk,
    const float* __restrict__ Wv,
    const float* __restrict__ Wo,
    float* __restrict__ outp,
    int mode)
{
    __shared__ float As[16][132];
    __shared__ float Bs[16][132];

    const int tid = threadIdx.x;
    const int tx  = tid & 15;
    const int ty  = tid >> 4;
    const int c0  = blockIdx.x * 128;
    const int m0  = blockIdx.y * 128;

    const float* A;
    const float* Bbase;
    float* C;
    int K, ldb, ldc;

    if (mode == 0) {
        A = x; K = D_DIM; C = g_tmp; ldc = QKV_W;
        const float* Wp; int cc;
        if (c0 < 4096)      { Wp = Wq; cc = c0; }
        else if (c0 < 6144) { Wp = Wk; cc = c0 - 4096; }
        else                { Wp = Wv; cc = c0 - 6144; }
        int n  = cc >> 8;
        int h0 = cc & 255;
        Bbase = Wp + (size_t)n * D_DIM * HD + h0;
        ldb = HD;
    } else {
        A = g_av; K = NQH * HD; C = outp; ldc = D_DIM;
        Bbase = Wo + c0;
        ldb = D_DIM;
    }

    float acc[8][8];
#pragma unroll
    for (int i = 0; i < 8; i++)
#pragma unroll
        for (int j = 0; j < 8; j++) acc[i][j] = 0.f;

    for (int k0 = 0; k0 < K; k0 += 16) {
        // Load A tile (128 rows x 16 k), store transposed As[k][m]
#pragma unroll
        for (int u = 0; u < 2; u++) {
            int idx = tid + u * 256;          // 0..511
            int row = idx >> 2;               // 0..127
            int kq  = (idx & 3) << 2;         // 0,4,8,12
            float4 a = *(const float4*)&A[(size_t)(m0 + row) * K + k0 + kq];
            As[kq + 0][row] = a.x;
            As[kq + 1][row] = a.y;
            As[kq + 2][row] = a.z;
            As[kq + 3][row] = a.w;
        }
        // Load B tile (16 k x 128 cols)
#pragma unroll
        for (int u = 0; u < 2; u++) {
            int idx = tid + u * 256;
            int row = idx >> 5;               // 0..15
            int c4  = (idx & 31) << 2;        // 0..124
            float4 b = *(const float4*)&Bbase[(size_t)(k0 + row) * ldb + c4];
            *(float4*)&Bs[row][c4] = b;
        }
        __syncthreads();

#pragma unroll
        for (int kk = 0; kk < 16; kk++) {
            float a[8], b[8];
            *(float4*)&a[0] = *(const float4*)&As[kk][ty * 8];
            *(float4*)&a[4] = *(const float4*)&As[kk][ty * 8 + 4];
            *(float4*)&b[0] = *(const float4*)&Bs[kk][tx * 8];
            *(float4*)&b[4] = *(const float4*)&Bs[kk][tx * 8 + 4];
#pragma unroll
            for (int i = 0; i < 8; i++)
#pragma unroll
                for (int j = 0; j < 8; j++)
                    acc[i][j] += a[i] * b[j];
        }
        __syncthreads();
    }

#pragma unroll
    for (int i = 0; i < 8; i++) {
        size_t base = (size_t)(m0 + ty * 8 + i) * ldc + c0 + tx * 8;
        float4 o0 = make_float4(acc[i][0], acc[i][1], acc[i][2], acc[i][3]);
        float4 o1 = make_float4(acc[i][4], acc[i][5], acc[i][6], acc[i][7]);
        *(float4*)&C[base]     = o0;
        *(float4*)&C[base + 4] = o1;
    }
}

// ---------------------------------------------------------------------------
// RoPE (in place on g_tmp, q & k heads only). Pair (h, h+128) within each head.
// No interleave needed: q·k is invariant to the identical output permutation.
// q additionally scaled by 1/sqrt(256) = 1/16.
// ---------------------------------------------------------------------------
__global__ __launch_bounds__(256) void rope_kernel()
{
    // total = TOKENS * 24 heads * 128 pairs
    int idx = blockIdx.x * 256 + threadIdx.x;
    const int total = TOKENS * 24 * 128;
    if (idx >= total) return;

    int pair  = idx & 127;
    int rem   = idx >> 7;
    int head  = rem % 24;          // 0..15 = q heads, 16..23 = k heads
    int token = rem / 24;          // b*S + t
    int t     = token & (S_LEN - 1);

    // inv_freq = 10000^(-pair/128)
    float inv = __expf(-(float)pair * (9.210340371976184f / 128.f));
    float ang = (float)t * inv;
    float sn, cs;
    sincosf(ang, &sn, &cs);

    size_t base = (size_t)token * QKV_W + head * HD + pair;
    float x1 = g_tmp[base];
    float x2 = g_tmp[base + 128];
    float r1 = x1 * cs - x2 * sn;
    float r2 = x2 * cs + x1 * sn;
    if (head < NQH) { r1 *= 0.0625f; r2 *= 0.0625f; }
    g_tmp[base]       = r1;
    g_tmp[base + 128] = r2;
}

// ---------------------------------------------------------------------------
// Flash attention, 64-query tiles, sliding-window causal, tanh softcap.
// grid (S/64, NQ, B), 256 threads. smem: Q tile + K/V tile (reused) + P + stats.
// ---------------------------------------------------------------------------
#define ROWP 260   // padded row stride (floats) for Q/KV tiles
#define ATT_SMEM_FLOATS (2 * 64 * ROWP + 64 * 64 + 3 * 64)
#define ATT_SMEM_BYTES  (ATT_SMEM_FLOATS * 4)

__global__ __launch_bounds__(256) void attn_kernel()
{
    extern __shared__ float sm[];
    float* Qs   = sm;                    // 64 x ROWP
    float* KVs  = Qs + 64 * ROWP;        // 64 x ROWP
    float* Ps   = KVs + 64 * ROWP;       // 64 x 64
    float* mrow = Ps + 64 * 64;          // 64
    float* lrow = mrow + 64;             // 64
    float* crow = lrow + 64;             // 64

    const int tid = threadIdx.x;
    const int t0  = blockIdx.x * 64;
    const int n   = blockIdx.y;
    const int b   = blockIdx.z;
    const int kvh = n >> 1;              // G = 2

    const int qcol = n * HD;
    const int kcol = 4096 + kvh * HD;
    const int vcol = 6144 + kvh * HD;

    // Load Q tile
    for (int i = tid; i < 64 * 64; i += 256) {
        int r = i >> 6, c4 = (i & 63) << 2;
        float4 v = *(const float4*)&g_tmp[((size_t)(b * S_LEN + t0 + r) << 13) + qcol + c4];
        *(float4*)&Qs[r * ROWP + c4] = v;
    }
    if (tid < 64) { mrow[tid] = -1e9f; lrow[tid] = 0.f; }

    float acc[8][8];
#pragma unroll
    for (int i = 0; i < 8; i++)
#pragma unroll
        for (int j = 0; j < 8; j++) acc[i][j] = 0.f;

    const int tx  = tid & 15;   // S-phase: keys tx + 16j
    const int ty  = tid >> 4;   // S-phase: queries ty*4 + i
    const int tx2 = tid & 31;   // PV: h = tx2*4 + {0..3} and 128 + tx2*4 + {0..3}
    const int ty2 = tid >> 5;   // PV: q rows ty2*8 + i

    const int s_begin = (t0 >= WINDOW) ? (t0 - WINDOW) : 0;

    for (int s0 = s_begin; s0 <= t0; s0 += 64) {
        // Load K tile
        for (int i = tid; i < 64 * 64; i += 256) {
            int r = i >> 6, c4 = (i & 63) << 2;
            float4 v = *(const float4*)&g_tmp[((size_t)(b * S_LEN + s0 + r) << 13) + kcol + c4];
            *(float4*)&KVs[r * ROWP + c4] = v;
        }
        __syncthreads();

        // S = Q K^T (each thread 4 queries x 4 keys)
        float s4[4][4];
#pragma unroll
        for (int i = 0; i < 4; i++)
#pragma unroll
            for (int j = 0; j < 4; j++) s4[i][j] = 0.f;

        for (int h4 = 0; h4 < 64; h4++) {
            float4 qv[4], kv4[4];
#pragma unroll
            for (int i = 0; i < 4; i++)
                qv[i] = *(const float4*)&Qs[(ty * 4 + i) * ROWP + h4 * 4];
#pragma unroll
            for (int j = 0; j < 4; j++)
                kv4[j] = *(const float4*)&KVs[(tx + 16 * j) * ROWP + h4 * 4];
#pragma unroll
            for (int i = 0; i < 4; i++)
#pragma unroll
                for (int j = 0; j < 4; j++)
                    s4[i][j] += qv[i].x * kv4[j].x + qv[i].y * kv4[j].y +
                                qv[i].z * kv4[j].z + qv[i].w * kv4[j].w;
        }

        // softcap + sliding-window causal mask -> P
#pragma unroll
        for (int i = 0; i < 4; i++) {
            int tq = t0 + ty * 4 + i;
#pragma unroll
            for (int j = 0; j < 4; j++) {
                int sk = s0 + tx + 16 * j;
                float lg = tanhf(s4[i][j] * (1.f / 50.f)) * 50.f;
                bool valid = (sk <= tq) && (sk > tq - WINDOW);
                Ps[(ty * 4 + i) * 64 + tx + 16 * j] = valid ? lg : -1e9f;
            }
        }
        __syncthreads();

        // Online softmax per row
        if (tid < 64) {
            float* prow = Ps + tid * 64;
            float mold = mrow[tid];
            float mt = mold;
#pragma unroll 8
            for (int j = 0; j < 64; j++) mt = fmaxf(mt, prow[j]);
            float c = __expf(mold - mt);
            float sum = 0.f;
#pragma unroll 8
            for (int j = 0; j < 64; j++) {
                float p = __expf(prow[j] - mt);
                prow[j] = p;
                sum += p;
            }
            lrow[tid] = lrow[tid] * c + sum;
            mrow[tid] = mt;
            crow[tid] = c;
        }
        __syncthreads();

        // Load V tile into KVs (K consumed), rescale accumulators meanwhile
        for (int i = tid; i < 64 * 64; i += 256) {
            int r = i >> 6, c4 = (i & 63) << 2;
            float4 v = *(const float4*)&g_tmp[((size_t)(b * S_LEN + s0 + r) << 13) + vcol + c4];
            *(float4*)&KVs[r * ROWP + c4] = v;
        }
#pragma unroll
        for (int i = 0; i < 8; i++) {
            float c = crow[ty2 * 8 + i];
#pragma unroll
            for (int j = 0; j < 8; j++) acc[i][j] *= c;
        }
        __syncthreads();

        // acc += P @ V
        for (int s = 0; s < 64; s++) {
            float4 v0 = *(const float4*)&KVs[s * ROWP + tx2 * 4];
            float4 v1 = *(const float4*)&KVs[s * ROWP + 128 + tx2 * 4];
#pragma unroll
            for (int i = 0; i < 8; i++) {
                float p = Ps[(ty2 * 8 + i) * 64 + s];
                acc[i][0] += p * v0.x; acc[i][1] += p * v0.y;
                acc[i][2] += p * v0.z; acc[i][3] += p * v0.w;
                acc[i][4] += p * v1.x; acc[i][5] += p * v1.y;
                acc[i][6] += p * v1.z; acc[i][7] += p * v1.w;
            }
        }
        __syncthreads();
    }

    // Finalize and write av[b, t, n*256 + h]
#pragma unroll
    for (int i = 0; i < 8; i++) {
        int r = ty2 * 8 + i;
        float inv = 1.f / lrow[r];
        size_t base = ((size_t)(b * S_LEN + t0 + r) << 12) + n * HD;
        float4 o0 = make_float4(acc[i][0] * inv, acc[i][1] * inv, acc[i][2] * inv, acc[i][3] * inv);
        float4 o1 = make_float4(acc[i][4] * inv, acc[i][5] * inv, acc[i][6] * inv, acc[i][7] * inv);
        *(float4*)&g_av[base + tx2 * 4]       = o0;
        *(float4*)&g_av[base + 128 + tx2 * 4] = o1;
    }
}

// ---------------------------------------------------------------------------
extern "C" void kernel_launch(void* const* d_in, const int* in_sizes, int n_in,
                              void* d_out, int out_size)
{
    (void)in_sizes; (void)n_in; (void)out_size;
    const float* x  = (const float*)d_in[0];
    const float* Wq = (const float*)d_in[1];
    const float* Wk = (const float*)d_in[2];
    const float* Wv = (const float*)d_in[3];
    const float* Wo = (const float*)d_in[4];
    float* out = (float*)d_out;

    cudaFuncSetAttribute(attn_kernel, cudaFuncAttributeMaxDynamicSharedMemorySize,
                         ATT_SMEM_BYTES);

    // 1) fused QKV projection: C[4096, 8192]
    sgemm_kernel<<<dim3(QKV_W / 128, TOKENS / 128), 256>>>(x, Wq, Wk, Wv, Wo, out, 0);

    // 2) RoPE in place on q,k heads
    {
        int total = TOKENS * 24 * 128;
        rope_kernel<<<(total + 255) / 256, 256>>>();
    }

    // 3) sliding-window flash attention -> g_av
    attn_kernel<<<dim3(S_LEN / 64, NQH, BATCH), 256, ATT_SMEM_BYTES>>>();

    // 4) output projection: out[4096, 2048] = g_av @ Wo
    sgemm_kernel<<<dim3(D_DIM / 128, TOKENS / 128), 256>>>(x, Wq, Wk, Wv, Wo, out, 1);
}

// round 8
// speedup vs baseline: 1.1404x; 1.1404x over previous
#include <cuda_runtime.h>
#include <cuda_bf16.h>
#include <math.h>
#include <stdint.h>

// Problem constants
#define BATCH   2
#define S_LEN   2048
#define D_DIM   2048
#define NQH     16
#define NKVH    8
#define HD      256
#define WINDOW  1024

#define QKV_W   8192
#define TOKENS  (BATCH * S_LEN)          // 4096

// Scratch (device globals — no allocation allowed)
__device__ float g_tmp[(size_t)TOKENS * QKV_W];      // qkv projections (rope in place)
__device__ float g_av [(size_t)TOKENS * (NQH * HD)]; // attention output [b,t,n*256+h]

// ---------------------------------------------------------------------------
// mma.sync m16n8k16 bf16 (baseline PTX — valid on sm_103 family target)
// D(f32) += A(bf16) * B(bf16);  A row-major frag, B col-major frag.
// ---------------------------------------------------------------------------
__device__ __forceinline__ void mma16816(float* d, const uint32_t* a, const uint32_t* b) {
    asm volatile(
        "mma.sync.aligned.m16n8k16.row.col.f32.bf16.bf16.f32 "
        "{%0,%1,%2,%3}, {%4,%5,%6,%7}, {%8,%9}, {%0,%1,%2,%3};"
        : "+f"(d[0]), "+f"(d[1]), "+f"(d[2]), "+f"(d[3])
        : "r"(a[0]), "r"(a[1]), "r"(a[2]), "r"(a[3]), "r"(b[0]), "r"(b[1]));
}

__device__ __forceinline__ void split_bf16(float v, float& h, float& l) {
    __nv_bfloat16 hb = __float2bfloat16_rn(v);
    h = __bfloat162float(hb);
    l = v - h;
}
__device__ __forceinline__ uint32_t pack2(float a, float b) {
    __nv_bfloat162 t = __floats2bfloat162_rn(a, b);
    return *(uint32_t*)&t;
}

// ===========================================================================
// Split-bf16 HMMA GEMM: C = A @ B, fp32 in/out, ~fp32 accuracy.
// CTA tile 128x128, BK=32, 256 threads = 8 warps (2 M x 4 N), 64x32 per warp.
// mode 0: C[4096,8192] = x @ [Wq|Wk|Wv] (per-128-col tile inside one head)
// mode 1: C[4096,2048] = g_av @ Wo
// ===========================================================================
#define APAD 40   // bf16 row stride (conflict-free fragment access)

__global__ __launch_bounds__(256, 2) void mma_gemm(
    const float* __restrict__ x,
    const float* __restrict__ Wq,
    const float* __restrict__ Wk,
    const float* __restrict__ Wv,
    const float* __restrict__ Wo,
    float* __restrict__ outp,
    int mode)
{
    __shared__ __nv_bfloat16 sAh[128][APAD];
    __shared__ __nv_bfloat16 sAl[128][APAD];
    __shared__ __nv_bfloat16 sBh[128][APAD];   // [n][k]
    __shared__ __nv_bfloat16 sBl[128][APAD];

    const int tid = threadIdx.x;
    const int c0  = blockIdx.x * 128;
    const int m0  = blockIdx.y * 128;

    const float* A;
    const float* Bb;
    float* C;
    int K, lda, ldb, ldc;
    if (mode == 0) {
        A = x; lda = D_DIM; K = D_DIM; C = g_tmp; ldc = QKV_W;
        const float* Wp; int cc;
        if (c0 < 4096)      { Wp = Wq; cc = c0; }
        else if (c0 < 6144) { Wp = Wk; cc = c0 - 4096; }
        else                { Wp = Wv; cc = c0 - 6144; }
        Bb = Wp + (size_t)(cc >> 8) * D_DIM * HD + (cc & 255);
        ldb = HD;
    } else {
        A = g_av; lda = NQH * HD; K = NQH * HD; C = outp; ldc = D_DIM;
        Bb = Wo + c0; ldb = D_DIM;
    }

    const int wid = tid >> 5, lane = tid & 31;
    const int wr  = wid >> 2, wc = wid & 3;          // warp 2x4 grid
    const int lr  = lane >> 2;                       // 0..7
    const int lc  = (lane & 3) << 1;                 // 0,2,4,6

    // A-load mapping: thread t -> row t/2, col half (t&1)*16
    const int arow = tid >> 1;
    const int acol = (tid & 1) << 4;
    // B-load mapping: thread t -> k-row t/8, n-chunk (t&7)*16
    const int bkr = tid >> 3;
    const int bnb = (tid & 7) << 4;

    float acc[4][4][4];
#pragma unroll
    for (int i = 0; i < 4; i++)
#pragma unroll
        for (int j = 0; j < 4; j++)
#pragma unroll
            for (int e = 0; e < 4; e++) acc[i][j][e] = 0.f;

    for (int k0 = 0; k0 < K; k0 += 32) {
        // ---- stage A: 128 rows x 32 k (fp32 -> hi/lo bf16) ----
        {
            const float* Ap = A + (size_t)(m0 + arow) * lda + k0 + acol;
#pragma unroll
            for (int u = 0; u < 4; u++) {
                float4 v = *(const float4*)(Ap + u * 4);
                float h0,l0,h1,l1,h2,l2,h3,l3;
                split_bf16(v.x,h0,l0); split_bf16(v.y,h1,l1);
                split_bf16(v.z,h2,l2); split_bf16(v.w,h3,l3);
                int cc2 = acol + u * 4;
                *(uint32_t*)&sAh[arow][cc2]     = pack2(h0,h1);
                *(uint32_t*)&sAh[arow][cc2 + 2] = pack2(h2,h3);
                *(uint32_t*)&sAl[arow][cc2]     = pack2(l0,l1);
                *(uint32_t*)&sAl[arow][cc2 + 2] = pack2(l2,l3);
            }
        }
        // ---- stage B: 32 k x 128 n -> transposed Bt[n][k] hi/lo ----
        {
            const float* Bp = Bb + (size_t)(k0 + bkr) * ldb + bnb;
#pragma unroll
            for (int u = 0; u < 4; u++) {
                float4 v = *(const float4*)(Bp + u * 4);
                float vv[4] = {v.x, v.y, v.z, v.w};
#pragma unroll
                for (int j = 0; j < 4; j++) {
                    float h, l;
                    split_bf16(vv[j], h, l);
                    int n = bnb + u * 4 + j;
                    sBh[n][bkr] = __float2bfloat16_rn(h);
                    sBl[n][bkr] = __float2bfloat16_rn(l);
                }
            }
        }
        __syncthreads();

        // ---- compute: 2 k16 steps ----
#pragma unroll
        for (int kk = 0; kk < 32; kk += 16) {
            uint32_t bh[4][2], bl[4][2];
#pragma unroll
            for (int nt = 0; nt < 4; nt++) {
                int n = wc * 32 + nt * 8 + lr;
                int c = kk + lc;
                bh[nt][0] = *(const uint32_t*)&sBh[n][c];
                bh[nt][1] = *(const uint32_t*)&sBh[n][c + 8];
                bl[nt][0] = *(const uint32_t*)&sBl[n][c];
                bl[nt][1] = *(const uint32_t*)&sBl[n][c + 8];
            }
#pragma unroll
            for (int mt = 0; mt < 4; mt++) {
                int r = wr * 64 + mt * 16 + lr;
                int c = kk + lc;
                uint32_t ah[4], al[4];
                ah[0] = *(const uint32_t*)&sAh[r][c];
                ah[1] = *(const uint32_t*)&sAh[r + 8][c];
                ah[2] = *(const uint32_t*)&sAh[r][c + 8];
                ah[3] = *(const uint32_t*)&sAh[r + 8][c + 8];
                al[0] = *(const uint32_t*)&sAl[r][c];
                al[1] = *(const uint32_t*)&sAl[r + 8][c];
                al[2] = *(const uint32_t*)&sAl[r][c + 8];
                al[3] = *(const uint32_t*)&sAl[r + 8][c + 8];
#pragma unroll
                for (int nt = 0; nt < 4; nt++) {
                    mma16816(acc[mt][nt], ah, bh[nt]);
                    mma16816(acc[mt][nt], al, bh[nt]);
                    mma16816(acc[mt][nt], ah, bl[nt]);
                }
            }
        }
        __syncthreads();
    }

    // ---- epilogue: fragment -> gmem fp32 ----
#pragma unroll
    for (int mt = 0; mt < 4; mt++) {
        int r = m0 + wr * 64 + mt * 16 + lr;
#pragma unroll
        for (int nt = 0; nt < 4; nt++) {
            int cc2 = c0 + wc * 32 + nt * 8 + lc;
            float2 d0 = make_float2(acc[mt][nt][0], acc[mt][nt][1]);
            float2 d1 = make_float2(acc[mt][nt][2], acc[mt][nt][3]);
            *(float2*)&C[(size_t)r * ldc + cc2]       = d0;
            *(float2*)&C[(size_t)(r + 8) * ldc + cc2] = d1;
        }
    }
}

// ---------------------------------------------------------------------------
// RoPE (in place on g_tmp, q & k heads only). Pair (h, h+128) within each head.
// q additionally scaled by 1/16.
// ---------------------------------------------------------------------------
__global__ __launch_bounds__(256) void rope_kernel()
{
    int idx = blockIdx.x * 256 + threadIdx.x;
    const int total = TOKENS * 24 * 128;
    if (idx >= total) return;

    int pair  = idx & 127;
    int rem   = idx >> 7;
    int head  = rem % 24;
    int token = rem / 24;
    int t     = token & (S_LEN - 1);

    float inv = __expf(-(float)pair * (9.210340371976184f / 128.f));
    float ang = (float)t * inv;
    float sn, cs;
    sincosf(ang, &sn, &cs);

    size_t base = (size_t)token * QKV_W + head * HD + pair;
    float x1 = g_tmp[base];
    float x2 = g_tmp[base + 128];
    float r1 = x1 * cs - x2 * sn;
    float r2 = x2 * cs + x1 * sn;
    if (head < NQH) { r1 *= 0.0625f; r2 *= 0.0625f; }
    g_tmp[base]       = r1;
    g_tmp[base + 128] = r2;
}

// ---------------------------------------------------------------------------
// Flash attention, 64-query tiles, sliding-window causal, tanh softcap (fp32).
// (unchanged from R1 — validated, rel_err 5.9e-6)
// ---------------------------------------------------------------------------
#define ROWP 260
#define ATT_SMEM_FLOATS (2 * 64 * ROWP + 64 * 64 + 3 * 64)
#define ATT_SMEM_BYTES  (ATT_SMEM_FLOATS * 4)

__global__ __launch_bounds__(256) void attn_kernel()
{
    extern __shared__ float sm[];
    float* Qs   = sm;
    float* KVs  = Qs + 64 * ROWP;
    float* Ps   = KVs + 64 * ROWP;
    float* mrow = Ps + 64 * 64;
    float* lrow = mrow + 64;
    float* crow = lrow + 64;

    const int tid = threadIdx.x;
    const int t0  = blockIdx.x * 64;
    const int n   = blockIdx.y;
    const int b   = blockIdx.z;
    const int kvh = n >> 1;

    const int qcol = n * HD;
    const int kcol = 4096 + kvh * HD;
    const int vcol = 6144 + kvh * HD;

    for (int i = tid; i < 64 * 64; i += 256) {
        int r = i >> 6, c4 = (i & 63) << 2;
        float4 v = *(const float4*)&g_tmp[((size_t)(b * S_LEN + t0 + r) << 13) + qcol + c4];
        *(float4*)&Qs[r * ROWP + c4] = v;
    }
    if (tid < 64) { mrow[tid] = -1e9f; lrow[tid] = 0.f; }

    float acc[8][8];
#pragma unroll
    for (int i = 0; i < 8; i++)
#pragma unroll
        for (int j = 0; j < 8; j++) acc[i][j] = 0.f;

    const int tx  = tid & 15;
    const int ty  = tid >> 4;
    const int tx2 = tid & 31;
    const int ty2 = tid >> 5;

    const int s_begin = (t0 >= WINDOW) ? (t0 - WINDOW) : 0;

    for (int s0 = s_begin; s0 <= t0; s0 += 64) {
        for (int i = tid; i < 64 * 64; i += 256) {
            int r = i >> 6, c4 = (i & 63) << 2;
            float4 v = *(const float4*)&g_tmp[((size_t)(b * S_LEN + s0 + r) << 13) + kcol + c4];
            *(float4*)&KVs[r * ROWP + c4] = v;
        }
        __syncthreads();

        float s4[4][4];
#pragma unroll
        for (int i = 0; i < 4; i++)
#pragma unroll
            for (int j = 0; j < 4; j++) s4[i][j] = 0.f;

        for (int h4 = 0; h4 < 64; h4++) {
            float4 qv[4], kv4[4];
#pragma unroll
            for (int i = 0; i < 4; i++)
                qv[i] = *(const float4*)&Qs[(ty * 4 + i) * ROWP + h4 * 4];
#pragma unroll
            for (int j = 0; j < 4; j++)
                kv4[j] = *(const float4*)&KVs[(tx + 16 * j) * ROWP + h4 * 4];
#pragma unroll
            for (int i = 0; i < 4; i++)
#pragma unroll
                for (int j = 0; j < 4; j++)
                    s4[i][j] += qv[i].x * kv4[j].x + qv[i].y * kv4[j].y +
                                qv[i].z * kv4[j].z + qv[i].w * kv4[j].w;
        }

#pragma unroll
        for (int i = 0; i < 4; i++) {
            int tq = t0 + ty * 4 + i;
#pragma unroll
            for (int j = 0; j < 4; j++) {
                int sk = s0 + tx + 16 * j;
                float lg = tanhf(s4[i][j] * (1.f / 50.f)) * 50.f;
                bool valid = (sk <= tq) && (sk > tq - WINDOW);
                Ps[(ty * 4 + i) * 64 + tx + 16 * j] = valid ? lg : -1e9f;
            }
        }
        __syncthreads();

        if (tid < 64) {
            float* prow = Ps + tid * 64;
            float mold = mrow[tid];
            float mt = mold;
#pragma unroll 8
            for (int j = 0; j < 64; j++) mt = fmaxf(mt, prow[j]);
            float c = __expf(mold - mt);
            float sum = 0.f;
#pragma unroll 8
            for (int j = 0; j < 64; j++) {
                float p = __expf(prow[j] - mt);
                prow[j] = p;
                sum += p;
            }
            lrow[tid] = lrow[tid] * c + sum;
            mrow[tid] = mt;
            crow[tid] = c;
        }
        __syncthreads();

        for (int i = tid; i < 64 * 64; i += 256) {
            int r = i >> 6, c4 = (i & 63) << 2;
            float4 v = *(const float4*)&g_tmp[((size_t)(b * S_LEN + s0 + r) << 13) + vcol + c4];
            *(float4*)&KVs[r * ROWP + c4] = v;
        }
#pragma unroll
        for (int i = 0; i < 8; i++) {
            float c = crow[ty2 * 8 + i];
#pragma unroll
            for (int j = 0; j < 8; j++) acc[i][j] *= c;
        }
        __syncthreads();

        for (int s = 0; s < 64; s++) {
            float4 v0 = *(const float4*)&KVs[s * ROWP + tx2 * 4];
            float4 v1 = *(const float4*)&KVs[s * ROWP + 128 + tx2 * 4];
#pragma unroll
            for (int i = 0; i < 8; i++) {
                float p = Ps[(ty2 * 8 + i) * 64 + s];
                acc[i][0] += p * v0.x; acc[i][1] += p * v0.y;
                acc[i][2] += p * v0.z; acc[i][3] += p * v0.w;
                acc[i][4] += p * v1.x; acc[i][5] += p * v1.y;
                acc[i][6] += p * v1.z; acc[i][7] += p * v1.w;
            }
        }
        __syncthreads();
    }

#pragma unroll
    for (int i = 0; i < 8; i++) {
        int r = ty2 * 8 + i;
        float inv = 1.f / lrow[r];
        size_t base = ((size_t)(b * S_LEN + t0 + r) << 12) + n * HD;
        float4 o0 = make_float4(acc[i][0] * inv, acc[i][1] * inv, acc[i][2] * inv, acc[i][3] * inv);
        float4 o1 = make_float4(acc[i][4] * inv, acc[i][5] * inv, acc[i][6] * inv, acc[i][7] * inv);
        *(float4*)&g_av[base + tx2 * 4]       = o0;
        *(float4*)&g_av[base + 128 + tx2 * 4] = o1;
    }
}

// ---------------------------------------------------------------------------
extern "C" void kernel_launch(void* const* d_in, const int* in_sizes, int n_in,
                              void* d_out, int out_size)
{
    (void)in_sizes; (void)n_in; (void)out_size;
    const float* x  = (const float*)d_in[0];
    const float* Wq = (const float*)d_in[1];
    const float* Wk = (const float*)d_in[2];
    const float* Wv = (const float*)d_in[3];
    const float* Wo = (const float*)d_in[4];
    float* out = (float*)d_out;

    cudaFuncSetAttribute(attn_kernel, cudaFuncAttributeMaxDynamicSharedMemorySize,
                         ATT_SMEM_BYTES);

    // 1) fused QKV projection: g_tmp[4096, 8192] = x @ [Wq|Wk|Wv]
    mma_gemm<<<dim3(QKV_W / 128, TOKENS / 128), 256>>>(x, Wq, Wk, Wv, Wo, out, 0);

    // 2) RoPE in place on q,k heads
    {
        int total = TOKENS * 24 * 128;
        rope_kernel<<<(total + 255) / 256, 256>>>();
    }

    // 3) sliding-window flash attention -> g_av
    attn_kernel<<<dim3(S_LEN / 64, NQH, BATCH), 256, ATT_SMEM_BYTES>>>();

    // 4) output projection: out[4096, 2048] = g_av @ Wo
    mma_gemm<<<dim3(D_DIM / 128, TOKENS / 128), 256>>>(x, Wq, Wk, Wv, Wo, out, 1);
}

// round 12
// speedup vs baseline: 1.4990x; 1.3145x over previous
#include <cuda_runtime.h>
#include <cuda_bf16.h>
#include <math.h>
#include <stdint.h>

// Problem constants
#define BATCH   2
#define S_LEN   2048
#define D_DIM   2048
#define NQH     16
#define NKVH    8
#define HD      256
#define WINDOW  1024

#define QKV_W   8192
#define TOKENS  (BATCH * S_LEN)          // 4096

// Scratch (device globals — no allocation allowed). 256B-aligned: cp.async
// requires 16B-aligned global addresses.
__device__ float g_tmp[(size_t)TOKENS * QKV_W];      // qkv projections fp32 (rope in place)
__device__ __align__(256) __nv_bfloat16 g_xh [(size_t)TOKENS * D_DIM];      // x split hi
__device__ __align__(256) __nv_bfloat16 g_xl [(size_t)TOKENS * D_DIM];      // x split lo
__device__ __align__(256) __nv_bfloat16 g_wth[(size_t)QKV_W * D_DIM];       // Wcat^T [n][k] hi
__device__ __align__(256) __nv_bfloat16 g_wtl[(size_t)QKV_W * D_DIM];       // lo
__device__ __align__(256) __nv_bfloat16 g_woth[(size_t)D_DIM * (NQH * HD)]; // Wo^T [n=d][k=nh] hi
__device__ __align__(256) __nv_bfloat16 g_wotl[(size_t)D_DIM * (NQH * HD)];
__device__ __align__(256) __nv_bfloat16 g_avh[(size_t)TOKENS * (NQH * HD)]; // attention out hi
__device__ __align__(256) __nv_bfloat16 g_avl[(size_t)TOKENS * (NQH * HD)]; // lo

// ---------------------------------------------------------------------------
// helpers
// ---------------------------------------------------------------------------
__device__ __forceinline__ void mma16816(float* d, const uint32_t* a, const uint32_t* b) {
    asm volatile(
        "mma.sync.aligned.m16n8k16.row.col.f32.bf16.bf16.f32 "
        "{%0,%1,%2,%3}, {%4,%5,%6,%7}, {%8,%9}, {%0,%1,%2,%3};"
        : "+f"(d[0]), "+f"(d[1]), "+f"(d[2]), "+f"(d[3])
        : "r"(a[0]), "r"(a[1]), "r"(a[2]), "r"(a[3]), "r"(b[0]), "r"(b[1]));
}
__device__ __forceinline__ void ldsm4(uint32_t* r, uint32_t saddr) {
    asm volatile("ldmatrix.sync.aligned.m8n8.x4.shared.b16 {%0,%1,%2,%3}, [%4];"
                 : "=r"(r[0]), "=r"(r[1]), "=r"(r[2]), "=r"(r[3]) : "r"(saddr));
}
__device__ __forceinline__ void cp16(uint32_t saddr, const void* gptr) {
    asm volatile("cp.async.cg.shared.global [%0], [%1], 16;" :: "r"(saddr), "l"(gptr));
}
__device__ __forceinline__ uint32_t smem_u32(const void* p) {
    uint32_t a;
    asm("{ .reg .u64 t; cvta.to.shared.u64 t, %1; cvt.u32.u64 %0, t; }" : "=r"(a) : "l"(p));
    return a;
}
__device__ __forceinline__ void split_bf16(float v, float& h, float& l) {
    __nv_bfloat16 hb = __float2bfloat16_rn(v);
    h = __bfloat162float(hb);
    l = v - h;
}
__device__ __forceinline__ uint32_t pack2(float a, float b) {
    __nv_bfloat162 t = __floats2bfloat162_rn(a, b);
    return *(uint32_t*)&t;
}

// ---------------------------------------------------------------------------
// Precompute kernels: split fp32 operands into (hi, lo) bf16 once per launch.
// ---------------------------------------------------------------------------
__global__ __launch_bounds__(256) void split_x_kernel(const float* __restrict__ src)
{
    size_t i = ((size_t)blockIdx.x * 256 + threadIdx.x) * 4;   // 8M elements total
    float4 v = *(const float4*)&src[i];
    float h0,l0,h1,l1,h2,l2,h3,l3;
    split_bf16(v.x,h0,l0); split_bf16(v.y,h1,l1);
    split_bf16(v.z,h2,l2); split_bf16(v.w,h3,l3);
    *(uint2*)&g_xh[i] = make_uint2(pack2(h0,h1), pack2(h2,h3));
    *(uint2*)&g_xl[i] = make_uint2(pack2(l0,l1), pack2(l2,l3));
}

// Wcat^T: g_wt[n][k] = W{q,k,v}[head][k][h] (n = concat col), split hi/lo.
__global__ void conv_wcat(const float* __restrict__ Wq,
                          const float* __restrict__ Wk,
                          const float* __restrict__ Wv)
{
    int n0 = blockIdx.x * 32, k0 = blockIdx.y * 32;
    const float* src; int h0;
    if (n0 < 4096)      { src = Wq + (size_t)(n0 >> 8) * D_DIM * HD; h0 = n0 & 255; }
    else if (n0 < 6144) { int c = n0 - 4096; src = Wk + (size_t)(c >> 8) * D_DIM * HD; h0 = c & 255; }
    else                { int c = n0 - 6144; src = Wv + (size_t)(c >> 8) * D_DIM * HD; h0 = c & 255; }
    __shared__ float t[32][33];
    int tx = threadIdx.x, ty = threadIdx.y;
#pragma unroll
    for (int i = 0; i < 4; i++)
        t[ty + 8*i][tx] = src[(size_t)(k0 + ty + 8*i) * HD + h0 + tx];
    __syncthreads();
#pragma unroll
    for (int i = 0; i < 4; i++) {
        int n = n0 + ty + 8*i, k = k0 + tx;
        float h, l; split_bf16(t[tx][ty + 8*i], h, l);
        g_wth[(size_t)n * D_DIM + k] = __float2bfloat16_rn(h);
        g_wtl[(size_t)n * D_DIM + k] = __float2bfloat16_rn(l);
    }
}

// Wo^T: g_wot[n=d][k=nh] = Wo[k][n], split hi/lo.
__global__ void conv_wo(const float* __restrict__ Wo)
{
    int n0 = blockIdx.x * 32, k0 = blockIdx.y * 32;
    __shared__ float t[32][33];
    int tx = threadIdx.x, ty = threadIdx.y;
#pragma unroll
    for (int i = 0; i < 4; i++)
        t[ty + 8*i][tx] = Wo[(size_t)(k0 + ty + 8*i) * D_DIM + n0 + tx];
    __syncthreads();
#pragma unroll
    for (int i = 0; i < 4; i++) {
        int n = n0 + ty + 8*i, k = k0 + tx;
        float h, l; split_bf16(t[tx][ty + 8*i], h, l);
        g_woth[(size_t)n * (NQH * HD) + k] = __float2bfloat16_rn(h);
        g_wotl[(size_t)n * (NQH * HD) + k] = __float2bfloat16_rn(l);
    }
}

// ===========================================================================
// bf16 split HMMA GEMM v2: cp.async double-buffer + ldmatrix.
// A [M][K] hi/lo bf16 row-major, B [N][K] hi/lo bf16 row-major, C [M][N] fp32.
// CTA 128x128, BK=32, 8 warps (2M x 4N), 64x32 per warp.
// mode 0: g_tmp = x(split) @ Wcat^T   M=4096 N=8192 K=2048
// mode 1: out   = av(split) @ Wo^T    M=4096 N=2048 K=4096
// ===========================================================================
#define APAD   40
#define TILE_B (128 * APAD * 2)          // one 128x32 bf16 tile = 10240 B
#define STAGE  (4 * TILE_B)              // Ah, Al, Bh, Bl = 40960 B
#define GSMEM  (2 * STAGE)               // 81920 B

__global__ __launch_bounds__(256) void gemm_bf16(float* __restrict__ outp, int mode)
{
    extern __shared__ char dsm[];
    const int tid = threadIdx.x;
    const int n0 = blockIdx.x * 128;
    const int m0 = blockIdx.y * 128;

    const __nv_bfloat16 *Ah, *Al, *Bh, *Bl;
    float* C;
    int N, K;
    if (mode == 0) {
        Ah = g_xh;  Al = g_xl;  Bh = g_wth;  Bl = g_wtl;
        C = g_tmp;  N = QKV_W;  K = D_DIM;
    } else {
        Ah = g_avh; Al = g_avl; Bh = g_woth; Bl = g_wotl;
        C = outp;   N = D_DIM;  K = NQH * HD;
    }
    const int nk = K >> 5;

    const uint32_t sbase = smem_u32(dsm);
    const int lane = tid & 31, wid = tid >> 5;
    const int wr = wid >> 2, wc = wid & 3;
    const int lr = lane >> 2, lc = (lane & 3) << 1;
    const int lrow = lane & 15, lcol = (lane >> 4) << 3;

    // cp.async mapping: thread -> (row, 16B chunk)
    const int crow = tid >> 2;
    const int ccol = (tid & 3) << 3;          // bf16 col 0,8,16,24
    const uint32_t soff = (uint32_t)(crow * APAD + ccol) * 2;

    float acc[4][4][4];
#pragma unroll
    for (int i = 0; i < 4; i++)
#pragma unroll
        for (int j = 0; j < 4; j++)
#pragma unroll
            for (int e = 0; e < 4; e++) acc[i][j][e] = 0.f;

    auto issue = [&](int slab, int buf) {
        const int k0 = slab << 5;
        const uint32_t sb = sbase + buf * STAGE + soff;
        const size_t ga = (size_t)(m0 + crow) * K + k0 + ccol;
        const size_t gb = (size_t)(n0 + crow) * K + k0 + ccol;
        cp16(sb,              Ah + ga);
        cp16(sb + TILE_B,     Al + ga);
        cp16(sb + 2 * TILE_B, Bh + gb);
        cp16(sb + 3 * TILE_B, Bl + gb);
        const size_t ga2 = ga + (size_t)64 * K;   // rows 64..127 (crow covers 0..63)
        const size_t gb2 = gb + (size_t)64 * K;
        const uint32_t sb2 = sb + (uint32_t)(64 * APAD * 2);
        cp16(sb2,              Ah + ga2);
        cp16(sb2 + TILE_B,     Al + ga2);
        cp16(sb2 + 2 * TILE_B, Bh + gb2);
        cp16(sb2 + 3 * TILE_B, Bl + gb2);
        asm volatile("cp.async.commit_group;" ::: "memory");
    };

    issue(0, 0);
    issue(1, 1);

    for (int i = 0; i < nk; i++) {
        if (i == nk - 1) asm volatile("cp.async.wait_group 0;" ::: "memory");
        else             asm volatile("cp.async.wait_group 1;" ::: "memory");
        __syncthreads();

        const uint32_t sb = sbase + (i & 1) * STAGE;
#pragma unroll
        for (int kk = 0; kk < 32; kk += 16) {
            uint32_t ah[4][4], bh2[2][4];
#pragma unroll
            for (int mt = 0; mt < 4; mt++)
                ldsm4(ah[mt], sb + (uint32_t)((wr*64 + mt*16 + lrow) * APAD + kk + lcol) * 2);
#pragma unroll
            for (int nb = 0; nb < 2; nb++)
                ldsm4(bh2[nb], sb + 2*TILE_B + (uint32_t)((wc*32 + nb*16 + lrow) * APAD + kk + lcol) * 2);
            // term 1: Ah * Bh
#pragma unroll
            for (int mt = 0; mt < 4; mt++)
#pragma unroll
                for (int nt = 0; nt < 4; nt++) {
                    uint32_t bb[2] = { bh2[nt>>1][nt&1], bh2[nt>>1][2 + (nt&1)] };
                    mma16816(acc[mt][nt], ah[mt], bb);
                }
            // term 2: Al * Bh
            {
                uint32_t al[4][4];
#pragma unroll
                for (int mt = 0; mt < 4; mt++)
                    ldsm4(al[mt], sb + TILE_B + (uint32_t)((wr*64 + mt*16 + lrow) * APAD + kk + lcol) * 2);
#pragma unroll
                for (int mt = 0; mt < 4; mt++)
#pragma unroll
                    for (int nt = 0; nt < 4; nt++) {
                        uint32_t bb[2] = { bh2[nt>>1][nt&1], bh2[nt>>1][2 + (nt&1)] };
                        mma16816(acc[mt][nt], al[mt], bb);
                    }
            }
            // term 3: Ah * Bl
            {
                uint32_t bl2[2][4];
#pragma unroll
                for (int nb = 0; nb < 2; nb++)
                    ldsm4(bl2[nb], sb + 3*TILE_B + (uint32_t)((wc*32 + nb*16 + lrow) * APAD + kk + lcol) * 2);
#pragma unroll
                for (int mt = 0; mt < 4; mt++)
#pragma unroll
                    for (int nt = 0; nt < 4; nt++) {
                        uint32_t bb[2] = { bl2[nt>>1][nt&1], bl2[nt>>1][2 + (nt&1)] };
                        mma16816(acc[mt][nt], ah[mt], bb);
                    }
            }
        }
        __syncthreads();
        if (i + 2 < nk) issue(i + 2, i & 1);
    }

    // epilogue
#pragma unroll
    for (int mt = 0; mt < 4; mt++) {
        int r = m0 + wr * 64 + mt * 16 + lr;
#pragma unroll
        for (int nt = 0; nt < 4; nt++) {
            int cc2 = n0 + wc * 32 + nt * 8 + lc;
            *(float2*)&C[(size_t)r * N + cc2]       = make_float2(acc[mt][nt][0], acc[mt][nt][1]);
            *(float2*)&C[(size_t)(r + 8) * N + cc2] = make_float2(acc[mt][nt][2], acc[mt][nt][3]);
        }
    }
}

// ---------------------------------------------------------------------------
// RoPE (in place on g_tmp, q & k heads only). q scaled by 1/16.
// ---------------------------------------------------------------------------
__global__ __launch_bounds__(256) void rope_kernel()
{
    int idx = blockIdx.x * 256 + threadIdx.x;
    const int total = TOKENS * 24 * 128;
    if (idx >= total) return;

    int pair  = idx & 127;
    int rem   = idx >> 7;
    int head  = rem % 24;
    int token = rem / 24;
    int t     = token & (S_LEN - 1);

    float inv = __expf(-(float)pair * (9.210340371976184f / 128.f));
    float ang = (float)t * inv;
    float sn, cs;
    sincosf(ang, &sn, &cs);

    size_t base = (size_t)token * QKV_W + head * HD + pair;
    float x1 = g_tmp[base];
    float x2 = g_tmp[base + 128];
    float r1 = x1 * cs - x2 * sn;
    float r2 = x2 * cs + x1 * sn;
    if (head < NQH) { r1 *= 0.0625f; r2 *= 0.0625f; }
    g_tmp[base]       = r1;
    g_tmp[base + 128] = r2;
}

// ---------------------------------------------------------------------------
// Flash attention (fp32 compute, validated) — epilogue emits hi/lo bf16.
// ---------------------------------------------------------------------------
#define ROWP 260
#define ATT_SMEM_FLOATS (2 * 64 * ROWP + 64 * 64 + 3 * 64)
#define ATT_SMEM_BYTES  (ATT_SMEM_FLOATS * 4)

__global__ __launch_bounds__(256) void attn_kernel()
{
    extern __shared__ float sm[];
    float* Qs   = sm;
    float* KVs  = Qs + 64 * ROWP;
    float* Ps   = KVs + 64 * ROWP;
    float* mrow = Ps + 64 * 64;
    float* lrow = mrow + 64;
    float* crow = lrow + 64;

    const int tid = threadIdx.x;
    const int t0  = blockIdx.x * 64;
    const int n   = blockIdx.y;
    const int b   = blockIdx.z;
    const int kvh = n >> 1;

    const int qcol = n * HD;
    const int kcol = 4096 + kvh * HD;
    const int vcol = 6144 + kvh * HD;

    for (int i = tid; i < 64 * 64; i += 256) {
        int r = i >> 6, c4 = (i & 63) << 2;
        float4 v = *(const float4*)&g_tmp[((size_t)(b * S_LEN + t0 + r) << 13) + qcol + c4];
        *(float4*)&Qs[r * ROWP + c4] = v;
    }
    if (tid < 64) { mrow[tid] = -1e9f; lrow[tid] = 0.f; }

    float acc[8][8];
#pragma unroll
    for (int i = 0; i < 8; i++)
#pragma unroll
        for (int j = 0; j < 8; j++) acc[i][j] = 0.f;

    const int tx  = tid & 15;
    const int ty  = tid >> 4;
    const int tx2 = tid & 31;
    const int ty2 = tid >> 5;

    const int s_begin = (t0 >= WINDOW) ? (t0 - WINDOW) : 0;

    for (int s0 = s_begin; s0 <= t0; s0 += 64) {
        for (int i = tid; i < 64 * 64; i += 256) {
            int r = i >> 6, c4 = (i & 63) << 2;
            float4 v = *(const float4*)&g_tmp[((size_t)(b * S_LEN + s0 + r) << 13) + kcol + c4];
            *(float4*)&KVs[r * ROWP + c4] = v;
        }
        __syncthreads();

        float s4[4][4];
#pragma unroll
        for (int i = 0; i < 4; i++)
#pragma unroll
            for (int j = 0; j < 4; j++) s4[i][j] = 0.f;

        for (int h4 = 0; h4 < 64; h4++) {
            float4 qv[4], kv4[4];
#pragma unroll
            for (int i = 0; i < 4; i++)
                qv[i] = *(const float4*)&Qs[(ty * 4 + i) * ROWP + h4 * 4];
#pragma unroll
            for (int j = 0; j < 4; j++)
                kv4[j] = *(const float4*)&KVs[(tx + 16 * j) * ROWP + h4 * 4];
#pragma unroll
            for (int i = 0; i < 4; i++)
#pragma unroll
                for (int j = 0; j < 4; j++)
                    s4[i][j] += qv[i].x * kv4[j].x + qv[i].y * kv4[j].y +
                                qv[i].z * kv4[j].z + qv[i].w * kv4[j].w;
        }

#pragma unroll
        for (int i = 0; i < 4; i++) {
            int tq = t0 + ty * 4 + i;
#pragma unroll
            for (int j = 0; j < 4; j++) {
                int sk = s0 + tx + 16 * j;
                float lg = tanhf(s4[i][j] * (1.f / 50.f)) * 50.f;
                bool valid = (sk <= tq) && (sk > tq - WINDOW);
                Ps[(ty * 4 + i) * 64 + tx + 16 * j] = valid ? lg : -1e9f;
            }
        }
        __syncthreads();

        if (tid < 64) {
            float* prow = Ps + tid * 64;
            float mold = mrow[tid];
            float mt = mold;
#pragma unroll 8
            for (int j = 0; j < 64; j++) mt = fmaxf(mt, prow[j]);
            float c = __expf(mold - mt);
            float sum = 0.f;
#pragma unroll 8
            for (int j = 0; j < 64; j++) {
                float p = __expf(prow[j] - mt);
                prow[j] = p;
                sum += p;
            }
            lrow[tid] = lrow[tid] * c + sum;
            mrow[tid] = mt;
            crow[tid] = c;
        }
        __syncthreads();

        for (int i = tid; i < 64 * 64; i += 256) {
            int r = i >> 6, c4 = (i & 63) << 2;
            float4 v = *(const float4*)&g_tmp[((size_t)(b * S_LEN + s0 + r) << 13) + vcol + c4];
            *(float4*)&KVs[r * ROWP + c4] = v;
        }
#pragma unroll
        for (int i = 0; i < 8; i++) {
            float c = crow[ty2 * 8 + i];
#pragma unroll
            for (int j = 0; j < 8; j++) acc[i][j] *= c;
        }
        __syncthreads();

        for (int s = 0; s < 64; s++) {
            float4 v0 = *(const float4*)&KVs[s * ROWP + tx2 * 4];
            float4 v1 = *(const float4*)&KVs[s * ROWP + 128 + tx2 * 4];
#pragma unroll
            for (int i = 0; i < 8; i++) {
                float p = Ps[(ty2 * 8 + i) * 64 + s];
                acc[i][0] += p * v0.x; acc[i][1] += p * v0.y;
                acc[i][2] += p * v0.z; acc[i][3] += p * v0.w;
                acc[i][4] += p * v1.x; acc[i][5] += p * v1.y;
                acc[i][6] += p * v1.z; acc[i][7] += p * v1.w;
            }
        }
        __syncthreads();
    }

    // finalize + split into hi/lo bf16 for the output GEMM
#pragma unroll
    for (int i = 0; i < 8; i++) {
        int r = ty2 * 8 + i;
        float inv = 1.f / lrow[r];
        size_t base = ((size_t)(b * S_LEN + t0 + r) << 12) + n * HD;
        float o[8], h[8], l[8];
#pragma unroll
        for (int j = 0; j < 8; j++) { o[j] = acc[i][j] * inv; split_bf16(o[j], h[j], l[j]); }
        *(uint2*)&g_avh[base + tx2 * 4]       = make_uint2(pack2(h[0],h[1]), pack2(h[2],h[3]));
        *(uint2*)&g_avh[base + 128 + tx2 * 4] = make_uint2(pack2(h[4],h[5]), pack2(h[6],h[7]));
        *(uint2*)&g_avl[base + tx2 * 4]       = make_uint2(pack2(l[0],l[1]), pack2(l[2],l[3]));
        *(uint2*)&g_avl[base + 128 + tx2 * 4] = make_uint2(pack2(l[4],l[5]), pack2(l[6],l[7]));
    }
}

// ---------------------------------------------------------------------------
extern "C" void kernel_launch(void* const* d_in, const int* in_sizes, int n_in,
                              void* d_out, int out_size)
{
    (void)in_sizes; (void)n_in; (void)out_size;
    const float* x  = (const float*)d_in[0];
    const float* Wq = (const float*)d_in[1];
    const float* Wk = (const float*)d_in[2];
    const float* Wv = (const float*)d_in[3];
    const float* Wo = (const float*)d_in[4];
    float* out = (float*)d_out;

    cudaFuncSetAttribute(gemm_bf16, cudaFuncAttributeMaxDynamicSharedMemorySize, GSMEM);
    cudaFuncSetAttribute(attn_kernel, cudaFuncAttributeMaxDynamicSharedMemorySize,
                         ATT_SMEM_BYTES);

    // 0) split fp32 operands into hi/lo bf16 (once per launch; ~40us)
    split_x_kernel<<<(TOKENS * D_DIM / 4 + 255) / 256, 256>>>(x);
    conv_wcat<<<dim3(QKV_W / 32, D_DIM / 32), dim3(32, 8)>>>(Wq, Wk, Wv);
    conv_wo<<<dim3(D_DIM / 32, (NQH * HD) / 32), dim3(32, 8)>>>(Wo);

    // 1) fused QKV projection: g_tmp[4096, 8192] = x @ [Wq|Wk|Wv]
    gemm_bf16<<<dim3(QKV_W / 128, TOKENS / 128), 256, GSMEM>>>(out, 0);

    // 2) RoPE in place on q,k heads
    {
        int total = TOKENS * 24 * 128;
        rope_kernel<<<(total + 255) / 256, 256>>>();
    }

    // 3) sliding-window flash attention -> g_avh/g_avl (split bf16)
    attn_kernel<<<dim3(S_LEN / 64, NQH, BATCH), 256, ATT_SMEM_BYTES>>>();

    // 4) output projection: out[4096, 2048] = av @ Wo
    gemm_bf16<<<dim3(D_DIM / 128, TOKENS / 128), 256, GSMEM>>>(out, 1);
}

// round 16
// speedup vs baseline: 2.0712x; 1.3817x over previous
#include <cuda_runtime.h>
#include <cuda_bf16.h>
#include <math.h>
#include <stdint.h>

// Problem constants
#define BATCH   2
#define S_LEN   2048
#define D_DIM   2048
#define NQH     16
#define NKVH    8
#define HD      256
#define WINDOW  1024

#define QKV_W   8192
#define TOKENS  (BATCH * S_LEN)          // 4096

// Scratch (device globals — no allocation allowed). 256B-aligned for cp.async.
__device__ float g_tmp[(size_t)TOKENS * QKV_W];      // qkv projections fp32 (pre-rope)
__device__ __align__(256) __nv_bfloat16 g_xh [(size_t)TOKENS * D_DIM];
__device__ __align__(256) __nv_bfloat16 g_xl [(size_t)TOKENS * D_DIM];
__device__ __align__(256) __nv_bfloat16 g_wth[(size_t)QKV_W * D_DIM];
__device__ __align__(256) __nv_bfloat16 g_wtl[(size_t)QKV_W * D_DIM];
__device__ __align__(256) __nv_bfloat16 g_woth[(size_t)D_DIM * (NQH * HD)];
__device__ __align__(256) __nv_bfloat16 g_wotl[(size_t)D_DIM * (NQH * HD)];
__device__ __align__(256) __nv_bfloat16 g_avh[(size_t)TOKENS * (NQH * HD)];
__device__ __align__(256) __nv_bfloat16 g_avl[(size_t)TOKENS * (NQH * HD)];
// attention operand arrays: per-head contiguous [b][head][s][hd], hi/lo bf16
__device__ __align__(256) __nv_bfloat16 g_qh[(size_t)BATCH * NQH  * S_LEN * HD];
__device__ __align__(256) __nv_bfloat16 g_ql[(size_t)BATCH * NQH  * S_LEN * HD];
__device__ __align__(256) __nv_bfloat16 g_kh[(size_t)BATCH * NKVH * S_LEN * HD];
__device__ __align__(256) __nv_bfloat16 g_kl[(size_t)BATCH * NKVH * S_LEN * HD];
__device__ __align__(256) __nv_bfloat16 g_vh[(size_t)BATCH * NKVH * S_LEN * HD];
__device__ __align__(256) __nv_bfloat16 g_vl[(size_t)BATCH * NKVH * S_LEN * HD];

// ---------------------------------------------------------------------------
// helpers (validated R8/R12)
// ---------------------------------------------------------------------------
__device__ __forceinline__ void mma16816(float* d, const uint32_t* a, const uint32_t* b) {
    asm volatile(
        "mma.sync.aligned.m16n8k16.row.col.f32.bf16.bf16.f32 "
        "{%0,%1,%2,%3}, {%4,%5,%6,%7}, {%8,%9}, {%0,%1,%2,%3};"
        : "+f"(d[0]), "+f"(d[1]), "+f"(d[2]), "+f"(d[3])
        : "r"(a[0]), "r"(a[1]), "r"(a[2]), "r"(a[3]), "r"(b[0]), "r"(b[1]));
}
__device__ __forceinline__ void ldsm4(uint32_t* r, uint32_t saddr) {
    asm volatile("ldmatrix.sync.aligned.m8n8.x4.shared.b16 {%0,%1,%2,%3}, [%4];"
                 : "=r"(r[0]), "=r"(r[1]), "=r"(r[2]), "=r"(r[3]) : "r"(saddr));
}
__device__ __forceinline__ void ldsm4t(uint32_t* r, uint32_t saddr) {
    asm volatile("ldmatrix.sync.aligned.m8n8.x4.trans.shared.b16 {%0,%1,%2,%3}, [%4];"
                 : "=r"(r[0]), "=r"(r[1]), "=r"(r[2]), "=r"(r[3]) : "r"(saddr));
}
__device__ __forceinline__ void cp16(uint32_t saddr, const void* gptr) {
    asm volatile("cp.async.cg.shared.global [%0], [%1], 16;" :: "r"(saddr), "l"(gptr));
}
__device__ __forceinline__ uint32_t smem_u32(const void* p) {
    uint32_t a;
    asm("{ .reg .u64 t; cvta.to.shared.u64 t, %1; cvt.u32.u64 %0, t; }" : "=r"(a) : "l"(p));
    return a;
}
__device__ __forceinline__ void split_bf16(float v, float& h, float& l) {
    __nv_bfloat16 hb = __float2bfloat16_rn(v);
    h = __bfloat162float(hb);
    l = v - h;
}
__device__ __forceinline__ uint32_t pack2(float a, float b) {
    __nv_bfloat162 t = __floats2bfloat162_rn(a, b);
    return *(uint32_t*)&t;
}

// ---------------------------------------------------------------------------
// Precompute: split fp32 operands into (hi, lo) bf16 (validated R12)
// ---------------------------------------------------------------------------
__global__ __launch_bounds__(256) void split_x_kernel(const float* __restrict__ src)
{
    size_t i = ((size_t)blockIdx.x * 256 + threadIdx.x) * 4;
    float4 v = *(const float4*)&src[i];
    float h0,l0,h1,l1,h2,l2,h3,l3;
    split_bf16(v.x,h0,l0); split_bf16(v.y,h1,l1);
    split_bf16(v.z,h2,l2); split_bf16(v.w,h3,l3);
    *(uint2*)&g_xh[i] = make_uint2(pack2(h0,h1), pack2(h2,h3));
    *(uint2*)&g_xl[i] = make_uint2(pack2(l0,l1), pack2(l2,l3));
}

__global__ void conv_wcat(const float* __restrict__ Wq,
                          const float* __restrict__ Wk,
                          const float* __restrict__ Wv)
{
    int n0 = blockIdx.x * 32, k0 = blockIdx.y * 32;
    const float* src; int h0;
    if (n0 < 4096)      { src = Wq + (size_t)(n0 >> 8) * D_DIM * HD; h0 = n0 & 255; }
    else if (n0 < 6144) { int c = n0 - 4096; src = Wk + (size_t)(c >> 8) * D_DIM * HD; h0 = c & 255; }
    else                { int c = n0 - 6144; src = Wv + (size_t)(c >> 8) * D_DIM * HD; h0 = c & 255; }
    __shared__ float t[32][33];
    int tx = threadIdx.x, ty = threadIdx.y;
#pragma unroll
    for (int i = 0; i < 4; i++)
        t[ty + 8*i][tx] = src[(size_t)(k0 + ty + 8*i) * HD + h0 + tx];
    __syncthreads();
#pragma unroll
    for (int i = 0; i < 4; i++) {
        int n = n0 + ty + 8*i, k = k0 + tx;
        float h, l; split_bf16(t[tx][ty + 8*i], h, l);
        g_wth[(size_t)n * D_DIM + k] = __float2bfloat16_rn(h);
        g_wtl[(size_t)n * D_DIM + k] = __float2bfloat16_rn(l);
    }
}

__global__ void conv_wo(const float* __restrict__ Wo)
{
    int n0 = blockIdx.x * 32, k0 = blockIdx.y * 32;
    __shared__ float t[32][33];
    int tx = threadIdx.x, ty = threadIdx.y;
#pragma unroll
    for (int i = 0; i < 4; i++)
        t[ty + 8*i][tx] = Wo[(size_t)(k0 + ty + 8*i) * D_DIM + n0 + tx];
    __syncthreads();
#pragma unroll
    for (int i = 0; i < 4; i++) {
        int n = n0 + ty + 8*i, k = k0 + tx;
        float h, l; split_bf16(t[tx][ty + 8*i], h, l);
        g_woth[(size_t)n * (NQH * HD) + k] = __float2bfloat16_rn(h);
        g_wotl[(size_t)n * (NQH * HD) + k] = __float2bfloat16_rn(l);
    }
}

// ===========================================================================
// bf16 split HMMA GEMM v2 (validated R12 — unchanged)
// ===========================================================================
#define APAD   40
#define TILE_B (128 * APAD * 2)
#define STAGE  (4 * TILE_B)
#define GSMEM  (2 * STAGE)

__global__ __launch_bounds__(256) void gemm_bf16(float* __restrict__ outp, int mode)
{
    extern __shared__ char dsm[];
    const int tid = threadIdx.x;
    const int n0 = blockIdx.x * 128;
    const int m0 = blockIdx.y * 128;

    const __nv_bfloat16 *Ah, *Al, *Bh, *Bl;
    float* C;
    int N, K;
    if (mode == 0) {
        Ah = g_xh;  Al = g_xl;  Bh = g_wth;  Bl = g_wtl;
        C = g_tmp;  N = QKV_W;  K = D_DIM;
    } else {
        Ah = g_avh; Al = g_avl; Bh = g_woth; Bl = g_wotl;
        C = outp;   N = D_DIM;  K = NQH * HD;
    }
    const int nk = K >> 5;

    const uint32_t sbase = smem_u32(dsm);
    const int lane = tid & 31, wid = tid >> 5;
    const int wr = wid >> 2, wc = wid & 3;
    const int lr = lane >> 2, lc = (lane & 3) << 1;
    const int lrow = lane & 15, lcol = (lane >> 4) << 3;

    const int crow = tid >> 2;
    const int ccol = (tid & 3) << 3;
    const uint32_t soff = (uint32_t)(crow * APAD + ccol) * 2;

    float acc[4][4][4];
#pragma unroll
    for (int i = 0; i < 4; i++)
#pragma unroll
        for (int j = 0; j < 4; j++)
#pragma unroll
            for (int e = 0; e < 4; e++) acc[i][j][e] = 0.f;

    auto issue = [&](int slab, int buf) {
        const int k0 = slab << 5;
        const uint32_t sb = sbase + buf * STAGE + soff;
        const size_t ga = (size_t)(m0 + crow) * K + k0 + ccol;
        const size_t gb = (size_t)(n0 + crow) * K + k0 + ccol;
        cp16(sb,              Ah + ga);
        cp16(sb + TILE_B,     Al + ga);
        cp16(sb + 2 * TILE_B, Bh + gb);
        cp16(sb + 3 * TILE_B, Bl + gb);
        const size_t ga2 = ga + (size_t)64 * K;
        const size_t gb2 = gb + (size_t)64 * K;
        const uint32_t sb2 = sb + (uint32_t)(64 * APAD * 2);
        cp16(sb2,              Ah + ga2);
        cp16(sb2 + TILE_B,     Al + ga2);
        cp16(sb2 + 2 * TILE_B, Bh + gb2);
        cp16(sb2 + 3 * TILE_B, Bl + gb2);
        asm volatile("cp.async.commit_group;" ::: "memory");
    };

    issue(0, 0);
    issue(1, 1);

    for (int i = 0; i < nk; i++) {
        if (i == nk - 1) asm volatile("cp.async.wait_group 0;" ::: "memory");
        else             asm volatile("cp.async.wait_group 1;" ::: "memory");
        __syncthreads();

        const uint32_t sb = sbase + (i & 1) * STAGE;
#pragma unroll
        for (int kk = 0; kk < 32; kk += 16) {
            uint32_t ah[4][4], bh2[2][4];
#pragma unroll
            for (int mt = 0; mt < 4; mt++)
                ldsm4(ah[mt], sb + (uint32_t)((wr*64 + mt*16 + lrow) * APAD + kk + lcol) * 2);
#pragma unroll
            for (int nb = 0; nb < 2; nb++)
                ldsm4(bh2[nb], sb + 2*TILE_B + (uint32_t)((wc*32 + nb*16 + lrow) * APAD + kk + lcol) * 2);
#pragma unroll
            for (int mt = 0; mt < 4; mt++)
#pragma unroll
                for (int nt = 0; nt < 4; nt++) {
                    uint32_t bb[2] = { bh2[nt>>1][nt&1], bh2[nt>>1][2 + (nt&1)] };
                    mma16816(acc[mt][nt], ah[mt], bb);
                }
            {
                uint32_t al[4][4];
#pragma unroll
                for (int mt = 0; mt < 4; mt++)
                    ldsm4(al[mt], sb + TILE_B + (uint32_t)((wr*64 + mt*16 + lrow) * APAD + kk + lcol) * 2);
#pragma unroll
                for (int mt = 0; mt < 4; mt++)
#pragma unroll
                    for (int nt = 0; nt < 4; nt++) {
                        uint32_t bb[2] = { bh2[nt>>1][nt&1], bh2[nt>>1][2 + (nt&1)] };
                        mma16816(acc[mt][nt], al[mt], bb);
                    }
            }
            {
                uint32_t bl2[2][4];
#pragma unroll
                for (int nb = 0; nb < 2; nb++)
                    ldsm4(bl2[nb], sb + 3*TILE_B + (uint32_t)((wc*32 + nb*16 + lrow) * APAD + kk + lcol) * 2);
#pragma unroll
                for (int mt = 0; mt < 4; mt++)
#pragma unroll
                    for (int nt = 0; nt < 4; nt++) {
                        uint32_t bb[2] = { bl2[nt>>1][nt&1], bl2[nt>>1][2 + (nt&1)] };
                        mma16816(acc[mt][nt], ah[mt], bb);
                    }
            }
        }
        __syncthreads();
        if (i + 2 < nk) issue(i + 2, i & 1);
    }

#pragma unroll
    for (int mt = 0; mt < 4; mt++) {
        int r = m0 + wr * 64 + mt * 16 + lr;
#pragma unroll
        for (int nt = 0; nt < 4; nt++) {
            int cc2 = n0 + wc * 32 + nt * 8 + lc;
            *(float2*)&C[(size_t)r * N + cc2]       = make_float2(acc[mt][nt][0], acc[mt][nt][1]);
            *(float2*)&C[(size_t)(r + 8) * N + cc2] = make_float2(acc[mt][nt][2], acc[mt][nt][3]);
        }
    }
}

// ---------------------------------------------------------------------------
// RoPE + split: read fp32 qkv from g_tmp, write hi/lo bf16 per-head arrays.
// heads 0-15: q (rope, 1/16 scale); 16-23: k (rope); 24-31: v (split only).
// ---------------------------------------------------------------------------
__global__ __launch_bounds__(256) void rope_split()
{
    int idx = blockIdx.x * 256 + threadIdx.x;
    const int total = TOKENS * 32 * 128;
    if (idx >= total) return;

    int pair  = idx & 127;
    int rem   = idx >> 7;
    int head  = rem & 31;
    int token = rem >> 5;
    int t     = token & (S_LEN - 1);
    int b     = token >> 11;

    size_t src = (size_t)token * QKV_W + head * HD + pair;
    float x1 = g_tmp[src];
    float x2 = g_tmp[src + 128];

    __nv_bfloat16 *dh, *dl;
    size_t dst;
    if (head < 24) {  // q or k: rope
        float inv = __expf(-(float)pair * (9.210340371976184f / 128.f));
        float ang = (float)t * inv;
        float sn, cs;
        sincosf(ang, &sn, &cs);
        float r1 = x1 * cs - x2 * sn;
        float r2 = x2 * cs + x1 * sn;
        if (head < NQH) {
            r1 *= 0.0625f; r2 *= 0.0625f;
            dh = g_qh; dl = g_ql;
            dst = (((size_t)(b * NQH + head) * S_LEN) + t) * HD + pair;
        } else {
            dh = g_kh; dl = g_kl;
            dst = (((size_t)(b * NKVH + (head - 16)) * S_LEN) + t) * HD + pair;
        }
        x1 = r1; x2 = r2;
    } else {          // v: plain split
        dh = g_vh; dl = g_vl;
        dst = (((size_t)(b * NKVH + (head - 24)) * S_LEN) + t) * HD + pair;
    }
    float h1, l1, h2, l2;
    split_bf16(x1, h1, l1); split_bf16(x2, h2, l2);
    dh[dst]       = __float2bfloat16_rn(h1);
    dh[dst + 128] = __float2bfloat16_rn(h2);
    dl[dst]       = __float2bfloat16_rn(l1);
    dl[dst + 128] = __float2bfloat16_rn(l2);
}

// ===========================================================================
// HMMA flash attention: 64q tile, 64-key steps, split-bf16 QK^T and PV.
// 256 threads = 8 warps (2M x 4N). smem: Q(hi/lo) resident, K/V shared buffer,
// S fp32, P hi/lo bf16, stats. Softmax semantics identical to R1 kernel.
// ===========================================================================
#define QST   264                         // Q/K/V smem row stride (bf16)
#define A_QH  0
#define A_QL  (A_QH + 64 * QST * 2)       // 33792
#define A_KH  (A_QL + 64 * QST * 2)       // 67584
#define A_KL  (A_KH + 64 * QST * 2)
#define A_PS  (A_KL + 64 * QST * 2)       // fp32 S, stride 68
#define A_PBH (A_PS + 64 * 68 * 4)        // P hi, stride 72
#define A_PBL (A_PBH + 64 * 72 * 2)
#define A_RED (A_PBL + 64 * 72 * 2)       // 4 x 64 fp32
#define A_MR  (A_RED + 4 * 64 * 4)
#define A_LR  (A_MR + 64 * 4)
#define A_CR  (A_LR + 64 * 4)
#define ASMEM (A_CR + 64 * 4)             // 172800

__global__ __launch_bounds__(256) void attn_mma()
{
    extern __shared__ char smb[];
    const uint32_t sb = smem_u32(smb);
    float* mrow = (float*)(smb + A_MR);
    float* lrw  = (float*)(smb + A_LR);
    float* crw  = (float*)(smb + A_CR);
    float* red  = (float*)(smb + A_RED);
    float* ps   = (float*)(smb + A_PS);

    const int tid  = threadIdx.x;
    const int lane = tid & 31, wid = tid >> 5;
    const int wr = wid >> 2, wc = wid & 3;
    const int lrow16 = lane & 15, lcol8 = (lane >> 4) << 3;

    const int t0 = blockIdx.x * 64;
    const int n  = blockIdx.y;
    const int b  = blockIdx.z;
    const int kvh = n >> 1;

    const __nv_bfloat16* qh = g_qh + ((size_t)(b * NQH + n) * S_LEN) * HD;
    const __nv_bfloat16* ql = g_ql + ((size_t)(b * NQH + n) * S_LEN) * HD;
    const size_t kvoff = ((size_t)(b * NKVH + kvh) * S_LEN) * HD;
    const __nv_bfloat16* kh = g_kh + kvoff;
    const __nv_bfloat16* kl = g_kl + kvoff;
    const __nv_bfloat16* vh = g_vh + kvoff;
    const __nv_bfloat16* vl = g_vl + kvoff;

    // loader mapping: 64 rows x 256 cols per array; thread -> row tid>>2, 8 chunks
    const int ldr = tid >> 2;
    const int ldc0 = tid & 3;

    auto load64 = [&](uint32_t smA, uint32_t smB,
                      const __nv_bfloat16* gA, const __nv_bfloat16* gB, int s0) {
#pragma unroll
        for (int u = 0; u < 8; u++) {
            int col = (ldc0 + 4 * u) << 3;          // 0..248
            uint32_t so = (uint32_t)(ldr * QST + col) * 2;
            size_t  go = (size_t)(s0 + ldr) * HD + col;
            cp16(smA + so, gA + go);
            cp16(smB + so, gB + go);
        }
        asm volatile("cp.async.commit_group;" ::: "memory");
    };

    // load Q (once) and first K
    const int s_begin = (t0 >= WINDOW) ? (t0 - WINDOW) : 0;
    load64(sb + A_QH, sb + A_QL, qh, ql, t0);
    load64(sb + A_KH, sb + A_KL, kh, kl, s_begin);
    if (tid < 64) { mrow[tid] = -1e9f; lrw[tid] = 0.f; }
    asm volatile("cp.async.wait_group 0;" ::: "memory");
    __syncthreads();

    float oacc[2][8][4];
#pragma unroll
    for (int i = 0; i < 2; i++)
#pragma unroll
        for (int j = 0; j < 8; j++)
#pragma unroll
            for (int e = 0; e < 4; e++) oacc[i][j][e] = 0.f;

    for (int s0 = s_begin; s0 <= t0; s0 += 64) {
        // ---- S = Q K^T (3-term split) ----
        float sacc[2][2][4];
#pragma unroll
        for (int i = 0; i < 2; i++)
#pragma unroll
            for (int j = 0; j < 2; j++)
#pragma unroll
                for (int e = 0; e < 4; e++) sacc[i][j][e] = 0.f;

#pragma unroll
        for (int ks = 0; ks < 16; ks++) {
            uint32_t qhf[2][4], qlf[2][4], khf[4], klf[4];
#pragma unroll
            for (int mt = 0; mt < 2; mt++) {
                uint32_t ro = (uint32_t)((wr*32 + mt*16 + lrow16) * QST + ks*16 + lcol8) * 2;
                ldsm4(qhf[mt], sb + A_QH + ro);
                ldsm4(qlf[mt], sb + A_QL + ro);
            }
            {
                uint32_t ro = (uint32_t)((wc*16 + lrow16) * QST + ks*16 + lcol8) * 2;
                ldsm4(khf, sb + A_KH + ro);
                ldsm4(klf, sb + A_KL + ro);
            }
#pragma unroll
            for (int mt = 0; mt < 2; mt++)
#pragma unroll
                for (int nt = 0; nt < 2; nt++) {
                    uint32_t bh[2] = { khf[nt], khf[2 + nt] };
                    uint32_t bl[2] = { klf[nt], klf[2 + nt] };
                    mma16816(sacc[mt][nt], qhf[mt], bh);
                    mma16816(sacc[mt][nt], qlf[mt], bh);
                    mma16816(sacc[mt][nt], qhf[mt], bl);
                }
        }

        // ---- softcap + mask, store to Ps (fp32) ----
#pragma unroll
        for (int mt = 0; mt < 2; mt++)
#pragma unroll
            for (int nt = 0; nt < 2; nt++)
#pragma unroll
                for (int e = 0; e < 4; e++) {
                    int rl = wr*32 + mt*16 + (lane >> 2) + ((e >> 1) << 3);
                    int cl = wc*16 + nt*8 + ((lane & 3) << 1) + (e & 1);
                    int tq = t0 + rl, sk = s0 + cl;
                    float lg = tanhf(sacc[mt][nt][e] * (1.f / 50.f)) * 50.f;
                    bool valid = (sk <= tq) && (sk > tq - WINDOW);
                    ps[rl * 68 + cl] = valid ? lg : -1e9f;
                }
        __syncthreads();   // all warps done with K smem + Ps visible

        // ---- prefetch V into K buffer (overlaps softmax) ----
        load64(sb + A_KH, sb + A_KL, vh, vl, s0);

        // ---- softmax (4 threads per row) ----
        const int srow = tid & 63, sq = tid >> 6;
        {
            float mt4 = -1e30f;
#pragma unroll
            for (int j = 0; j < 16; j++) mt4 = fmaxf(mt4, ps[srow * 68 + sq * 16 + j]);
            red[sq * 64 + srow] = mt4;
        }
        __syncthreads();
        if (tid < 64) {
            float m4 = fmaxf(fmaxf(red[tid], red[64 + tid]),
                             fmaxf(red[128 + tid], red[192 + tid]));
            float mold = mrow[tid];
            float mnew = fmaxf(mold, m4);
            crw[tid] = __expf(mold - mnew);
            mrow[tid] = mnew;
        }
        __syncthreads();
        {
            float mnew = mrow[srow];
            float sum = 0.f;
            __nv_bfloat16* pbh = (__nv_bfloat16*)(smb + A_PBH);
            __nv_bfloat16* pbl = (__nv_bfloat16*)(smb + A_PBL);
#pragma unroll
            for (int j = 0; j < 16; j++) {
                int cl = sq * 16 + j;
                float p = __expf(ps[srow * 68 + cl] - mnew);
                float h, l; split_bf16(p, h, l);
                pbh[srow * 72 + cl] = __float2bfloat16_rn(h);
                pbl[srow * 72 + cl] = __float2bfloat16_rn(l);
                sum += p;
            }
            red[sq * 64 + srow] = sum;
        }
        __syncthreads();
        if (tid < 64) {
            float s4 = red[tid] + red[64 + tid] + red[128 + tid] + red[192 + tid];
            lrw[tid] = lrw[tid] * crw[tid] + s4;
        }
        asm volatile("cp.async.wait_group 0;" ::: "memory");
        __syncthreads();   // V ready, Pb + stats visible

        // ---- rescale O ----
#pragma unroll
        for (int mt = 0; mt < 2; mt++) {
            float c0 = crw[wr*32 + mt*16 + (lane >> 2)];
            float c1 = crw[wr*32 + mt*16 + (lane >> 2) + 8];
#pragma unroll
            for (int nt = 0; nt < 8; nt++) {
                oacc[mt][nt][0] *= c0; oacc[mt][nt][1] *= c0;
                oacc[mt][nt][2] *= c1; oacc[mt][nt][3] *= c1;
            }
        }

        // ---- O += P V (3-term split, V via ldmatrix.trans) ----
#pragma unroll
        for (int kst = 0; kst < 4; kst++) {
            uint32_t pah[2][4], pal[2][4], vhf[4][4], vlf[4][4];
#pragma unroll
            for (int mt = 0; mt < 2; mt++) {
                uint32_t ro = (uint32_t)((wr*32 + mt*16 + lrow16) * 72 + kst*16 + lcol8) * 2;
                ldsm4(pah[mt], sb + A_PBH + ro);
                ldsm4(pal[mt], sb + A_PBL + ro);
            }
            {
                int vrow = kst*16 + (lane & 7) + (((lane >> 3) & 1) << 3);
#pragma unroll
                for (int np = 0; np < 4; np++) {
                    int vcol = wc*64 + np*16 + ((lane >> 4) << 3);
                    uint32_t ro = (uint32_t)(vrow * QST + vcol) * 2;
                    ldsm4t(vhf[np], sb + A_KH + ro);
                    ldsm4t(vlf[np], sb + A_KL + ro);
                }
            }
#pragma unroll
            for (int mt = 0; mt < 2; mt++)
#pragma unroll
                for (int nt = 0; nt < 8; nt++) {
                    int np = nt >> 1, od = (nt & 1) << 1;
                    uint32_t bh[2] = { vhf[np][od], vhf[np][od + 1] };
                    uint32_t bl[2] = { vlf[np][od], vlf[np][od + 1] };
                    mma16816(oacc[mt][nt], pah[mt], bh);
                    mma16816(oacc[mt][nt], pal[mt], bh);
                    mma16816(oacc[mt][nt], pah[mt], bl);
                }
        }
        __syncthreads();   // all warps done with V before next K overwrite

        if (s0 + 64 <= t0) {
            load64(sb + A_KH, sb + A_KL, kh, kl, s0 + 64);
            asm volatile("cp.async.wait_group 0;" ::: "memory");
        }
        __syncthreads();
    }

    // ---- finalize + split-write av ----
#pragma unroll
    for (int mt = 0; mt < 2; mt++) {
        int rl0 = wr*32 + mt*16 + (lane >> 2);
        float i0 = 1.f / lrw[rl0];
        float i1 = 1.f / lrw[rl0 + 8];
#pragma unroll
        for (int nt = 0; nt < 8; nt++) {
            int col = n * HD + wc*64 + nt*8 + ((lane & 3) << 1);
            {
                float o0 = oacc[mt][nt][0] * i0, o1 = oacc[mt][nt][1] * i0;
                float h0,l0,h1,l1; split_bf16(o0,h0,l0); split_bf16(o1,h1,l1);
                size_t base = (size_t)(b * S_LEN + t0 + rl0) * (NQH * HD) + col;
                *(uint32_t*)&g_avh[base] = pack2(h0, h1);
                *(uint32_t*)&g_avl[base] = pack2(l0, l1);
            }
            {
                float o2 = oacc[mt][nt][2] * i1, o3 = oacc[mt][nt][3] * i1;
                float h2,l2,h3,l3; split_bf16(o2,h2,l2); split_bf16(o3,h3,l3);
                size_t base = (size_t)(b * S_LEN + t0 + rl0 + 8) * (NQH * HD) + col;
                *(uint32_t*)&g_avh[base] = pack2(h2, h3);
                *(uint32_t*)&g_avl[base] = pack2(l2, l3);
            }
        }
    }
}

// ---------------------------------------------------------------------------
extern "C" void kernel_launch(void* const* d_in, const int* in_sizes, int n_in,
                              void* d_out, int out_size)
{
    (void)in_sizes; (void)n_in; (void)out_size;
    const float* x  = (const float*)d_in[0];
    const float* Wq = (const float*)d_in[1];
    const float* Wk = (const float*)d_in[2];
    const float* Wv = (const float*)d_in[3];
    const float* Wo = (const float*)d_in[4];
    float* out = (float*)d_out;

    cudaFuncSetAttribute(gemm_bf16, cudaFuncAttributeMaxDynamicSharedMemorySize, GSMEM);
    cudaFuncSetAttribute(attn_mma, cudaFuncAttributeMaxDynamicSharedMemorySize, ASMEM);

    // 0) split fp32 operands into hi/lo bf16
    split_x_kernel<<<(TOKENS * D_DIM / 4 + 255) / 256, 256>>>(x);
    conv_wcat<<<dim3(QKV_W / 32, D_DIM / 32), dim3(32, 8)>>>(Wq, Wk, Wv);
    conv_wo<<<dim3(D_DIM / 32, (NQH * HD) / 32), dim3(32, 8)>>>(Wo);

    // 1) fused QKV projection
    gemm_bf16<<<dim3(QKV_W / 128, TOKENS / 128), 256, GSMEM>>>(out, 0);

    // 2) RoPE + split into per-head hi/lo bf16 operand arrays
    {
        int total = TOKENS * 32 * 128;
        rope_split<<<(total + 255) / 256, 256>>>();
    }

    // 3) HMMA sliding-window flash attention -> g_avh/g_avl
    attn_mma<<<dim3(S_LEN / 64, NQH, BATCH), 256, ASMEM>>>();

    // 4) output projection
    gemm_bf16<<<dim3(D_DIM / 128, TOKENS / 128), 256, GSMEM>>>(out, 1);
}